// round 6
// baseline (speedup 1.0000x reference)
#include <cuda_runtime.h>
#include <math.h>

#define BB    16
#define CINN  64
#define COUTT 64
#define HH    256
#define WW    256
#define M1N   32
#define M2N   32
#define KXN   64   // rows 0..31 and 224..255

// ---------------- scratch ----------------
// activations stored pre-split into tf32 (hi, lo) planes
__device__ float  g_Y1h[BB * CINN * HH * 64];          // 67MB
__device__ float  g_Y1l[BB * CINN * HH * 64];          // 67MB
__device__ float2 g_Xf  [BB * CINN  * KXN * M2N];      // fp32 complex
__device__ float2 g_T   [BB * COUTT * KXN * M2N];
__device__ float2 g_OutF[BB * COUTT * KXN * M2N];
__device__ float  g_Zh [BB * COUTT * HH * 64];         // 67MB
__device__ float  g_Zl [BB * COUTT * HH * 64];         // 67MB
// stationary matrices, pre-split
__device__ float g_B1h[256 * 64],  g_B1l[256 * 64];    // fwd W-DFT, scale 1/16
__device__ float g_A2h[128 * 512], g_A2l[128 * 512];   // fwd H-DFT, scale 1/16
__device__ float g_A5h[512 * 128], g_A5l[512 * 128];   // inv H-DFT
__device__ float g_C6h[64 * 256],  g_C6l[64 * 256];    // inv W (irfft), scale 1/256

// ---------------- tf32 helpers ----------------
__device__ __forceinline__ unsigned tf32of(float x) {
    unsigned r; asm("cvt.rna.tf32.f32 %0,%1;" : "=r"(r) : "f"(x)); return r;
}
__device__ __forceinline__ void split2(float x, unsigned& h, unsigned& l) {
    h = tf32of(x);
    l = tf32of(x - __uint_as_float(h));
}
__device__ __forceinline__ void split2f(float x, float& h, float& l) {
    unsigned hu = tf32of(x);
    h = __uint_as_float(hu);
    l = __uint_as_float(tf32of(x - h));
}
__device__ __forceinline__ unsigned B(float x) { return __float_as_uint(x); }

__device__ __forceinline__ void mma1(float* c, const unsigned* a, const unsigned* b) {
    asm volatile(
        "mma.sync.aligned.m16n8k8.row.col.f32.tf32.tf32.f32 "
        "{%0,%1,%2,%3},{%4,%5,%6,%7},{%8,%9},{%0,%1,%2,%3};"
        : "+f"(c[0]), "+f"(c[1]), "+f"(c[2]), "+f"(c[3])
        : "r"(a[0]), "r"(a[1]), "r"(a[2]), "r"(a[3]), "r"(b[0]), "r"(b[1]));
}
__device__ __forceinline__ void mma3(float* c, const unsigned* ah, const unsigned* al,
                                     const unsigned* bh, const unsigned* bl) {
    mma1(c, ah, bh);
    mma1(c, al, bh);
    mma1(c, ah, bl);
}

// ---------------- fill kernels (pre-split stationary matrices) ----------------
__global__ void __launch_bounds__(256) fill_B1() {
    int idx = blockIdx.x * 256 + threadIdx.x;           // 16384
    int w = idx >> 6, n = idx & 63, ky = n >> 1, t = n & 1;
    float s, c; sincospif((float)((w * ky) & 255) / 128.0f, &s, &c);
    float v = (t == 0 ? c : -s) * (1.0f / 16.0f);
    split2f(v, g_B1h[idx], g_B1l[idx]);
}
__global__ void __launch_bounds__(256) fill_A2() {
    int idx = blockIdx.x * 256 + threadIdx.x;           // 65536
    int row = idx >> 9, col = idx & 511;
    int kxi = row >> 1, t = row & 1, h = col >> 1, s2 = col & 1;
    int kx = (kxi < 32) ? kxi : (192 + kxi);
    float s, c; sincospif((float)((kx * h) & 255) / 128.0f, &s, &c);
    float v = ((t == 0) ? ((s2 == 0) ? c : s) : ((s2 == 0) ? -s : c)) * (1.0f / 16.0f);
    split2f(v, g_A2h[idx], g_A2l[idx]);
}
__global__ void __launch_bounds__(256) fill_A5() {
    int idx = blockIdx.x * 256 + threadIdx.x;           // 65536
    int row = idx >> 7, col = idx & 127;
    int h = row >> 1, t = row & 1, kxi = col >> 1, s2 = col & 1;
    int kx = (kxi < 32) ? kxi : (192 + kxi);
    float s, c; sincospif((float)((kx * h) & 255) / 128.0f, &s, &c);
    float v = (t == 0) ? ((s2 == 0) ? c : -s) : ((s2 == 0) ? s : c);
    split2f(v, g_A5h[idx], g_A5l[idx]);
}
__global__ void __launch_bounds__(256) fill_C6() {
    int idx = blockIdx.x * 256 + threadIdx.x;           // 16384
    int k = idx >> 8, w = idx & 255;
    int ky = k >> 1, t = k & 1;
    float s, c; sincospif((float)((ky * w) & 255) / 128.0f, &s, &c);
    float base = ((ky == 0) ? 1.0f : 2.0f) * (1.0f / 256.0f);
    float v = (t == 0) ? base * c : ((ky == 0) ? 0.0f : -base * s);
    split2f(v, g_C6h[idx], g_C6l[idx]);
}

// ---------------- S1: Y1 = x @ B1  (M=262144, K=256, N=64) ----------------
__global__ void __launch_bounds__(256) s1_wdft(const float* __restrict__ x) {
    __shared__ float sA [128][33];
    __shared__ float sBh[32][65];
    __shared__ float sBl[32][65];
    const int tid = threadIdx.x, warp = tid >> 5, lane = tid & 31;
    const int g = lane >> 2, tg = lane & 3;
    const int r0 = blockIdx.x * 128;

    float c[8][4];
#pragma unroll
    for (int i = 0; i < 8; i++)
#pragma unroll
        for (int j = 0; j < 4; j++) c[i][j] = 0.f;

    for (int kc = 0; kc < 8; kc++) {
        __syncthreads();
        for (int i = tid; i < 128 * 32; i += 256) {
            int row = i >> 5, col = i & 31;
            sA[row][col] = x[(size_t)(r0 + row) * 256 + kc * 32 + col];
        }
        for (int i = tid; i < 32 * 64; i += 256) {
            int k = i >> 6, n = i & 63;
            sBh[k][n] = g_B1h[(kc * 32 + k) * 64 + n];
            sBl[k][n] = g_B1l[(kc * 32 + k) * 64 + n];
        }
        __syncthreads();
#pragma unroll
        for (int ks = 0; ks < 4; ks++) {
            unsigned ah[4], al[4];
            split2(sA[warp * 16 + g    ][ks * 8 + tg    ], ah[0], al[0]);
            split2(sA[warp * 16 + g + 8][ks * 8 + tg    ], ah[1], al[1]);
            split2(sA[warp * 16 + g    ][ks * 8 + tg + 4], ah[2], al[2]);
            split2(sA[warp * 16 + g + 8][ks * 8 + tg + 4], ah[3], al[3]);
#pragma unroll
            for (int nt = 0; nt < 8; nt++) {
                unsigned bh[2], bl[2];
                bh[0] = B(sBh[ks * 8 + tg    ][nt * 8 + g]);
                bh[1] = B(sBh[ks * 8 + tg + 4][nt * 8 + g]);
                bl[0] = B(sBl[ks * 8 + tg    ][nt * 8 + g]);
                bl[1] = B(sBl[ks * 8 + tg + 4][nt * 8 + g]);
                mma3(c[nt], ah, al, bh, bl);
            }
        }
    }
#pragma unroll
    for (int nt = 0; nt < 8; nt++) {
        int row = r0 + warp * 16 + g;
        int col = nt * 8 + 2 * tg;
        float h0, l0, h1, l1, h2, l2, h3, l3;
        split2f(c[nt][0], h0, l0); split2f(c[nt][1], h1, l1);
        split2f(c[nt][2], h2, l2); split2f(c[nt][3], h3, l3);
        *(float2*)&g_Y1h[(size_t)row * 64 + col]       = make_float2(h0, h1);
        *(float2*)&g_Y1l[(size_t)row * 64 + col]       = make_float2(l0, l1);
        *(float2*)&g_Y1h[(size_t)(row + 8) * 64 + col] = make_float2(h2, h3);
        *(float2*)&g_Y1l[(size_t)(row + 8) * 64 + col] = make_float2(l2, l3);
    }
}

// ---------------- S2: Xf = A2 @ Y1slab  (per (b,i): M=128, K=512, N=32) ----------------
__global__ void __launch_bounds__(256) s2_hdft() {
    __shared__ float sAh[128][33];
    __shared__ float sAl[128][33];
    __shared__ float sYh[16][66];
    __shared__ float sYl[16][66];
    const int tid = threadIdx.x, warp = tid >> 5, lane = tid & 31;
    const int g = lane >> 2, tg = lane & 3;
    const int bi = blockIdx.x;

    float c[4][4];
#pragma unroll
    for (int i = 0; i < 4; i++)
#pragma unroll
        for (int j = 0; j < 4; j++) c[i][j] = 0.f;

    for (int kc = 0; kc < 16; kc++) {
        __syncthreads();
        for (int i = tid; i < 128 * 32; i += 256) {
            int row = i >> 5, col = i & 31;
            sAh[row][col] = g_A2h[row * 512 + kc * 32 + col];
            sAl[row][col] = g_A2l[row * 512 + kc * 32 + col];
        }
        for (int i = tid; i < 16 * 64; i += 256) {
            int h = i >> 6, cc = i & 63;
            size_t src = ((size_t)bi * 256 + kc * 16 + h) * 64 + cc;
            sYh[h][cc] = g_Y1h[src];
            sYl[h][cc] = g_Y1l[src];
        }
        __syncthreads();
#pragma unroll
        for (int ks = 0; ks < 4; ks++) {
            unsigned ah[4], al[4];
            ah[0] = B(sAh[warp * 16 + g    ][ks * 8 + tg    ]);
            ah[1] = B(sAh[warp * 16 + g + 8][ks * 8 + tg    ]);
            ah[2] = B(sAh[warp * 16 + g    ][ks * 8 + tg + 4]);
            ah[3] = B(sAh[warp * 16 + g + 8][ks * 8 + tg + 4]);
            al[0] = B(sAl[warp * 16 + g    ][ks * 8 + tg    ]);
            al[1] = B(sAl[warp * 16 + g + 8][ks * 8 + tg    ]);
            al[2] = B(sAl[warp * 16 + g    ][ks * 8 + tg + 4]);
            al[3] = B(sAl[warp * 16 + g + 8][ks * 8 + tg + 4]);
            int k0 = ks * 8 + tg, k1 = k0 + 4;
#pragma unroll
            for (int nt = 0; nt < 4; nt++) {
                unsigned bh[2], bl[2];
                int n = nt * 8 + g;
                bh[0] = B(sYh[k0 >> 1][2 * n + (k0 & 1)]);
                bh[1] = B(sYh[k1 >> 1][2 * n + (k1 & 1)]);
                bl[0] = B(sYl[k0 >> 1][2 * n + (k0 & 1)]);
                bl[1] = B(sYl[k1 >> 1][2 * n + (k1 & 1)]);
                mma3(c[nt], ah, al, bh, bl);
            }
        }
    }
    float* xf = (float*)g_Xf + (size_t)bi * 4096;
#pragma unroll
    for (int nt = 0; nt < 4; nt++) {
        int m0 = warp * 16 + g, m1 = m0 + 8;
        int n0 = nt * 8 + 2 * tg, n1 = n0 + 1;
        xf[(m0 >> 1) * 64 + 2 * n0 + (m0 & 1)] = c[nt][0];
        xf[(m0 >> 1) * 64 + 2 * n1 + (m0 & 1)] = c[nt][1];
        xf[(m1 >> 1) * 64 + 2 * n0 + (m1 & 1)] = c[nt][2];
        xf[(m1 >> 1) * 64 + 2 * n1 + (m1 & 1)] = c[nt][3];
    }
}

// ---------------- K3a (FFMA): t = sum_i Xf * w{1|2} ----------------
__global__ void __launch_bounds__(256) k3a_mixx(const float* __restrict__ wx1,
                                                const float* __restrict__ wx2) {
    __shared__ float2 sX[CINN][M2N];
    __shared__ float2 sW[CINN][COUTT];
    const int tid = threadIdx.x;
    const int kxi = blockIdx.x, b = blockIdx.y;
    const int m = (kxi < 32) ? kxi : (kxi - 32);
    const float2* wsrc = (const float2*)((kxi < 32) ? wx1 : wx2);

    for (int idx = tid; idx < CINN * M2N; idx += 256) {
        int i = idx >> 5, k = idx & 31;
        sX[i][k] = g_Xf[((b * CINN + i) * KXN + kxi) * M2N + k];
    }
    for (int idx = tid; idx < CINN * COUTT; idx += 256) {
        int i = idx >> 6, c = idx & 63;
        sW[i][c] = wsrc[(i * COUTT + c) * M1N + m];
    }
    __syncthreads();

    const int ky = tid & 31;
    const int cb = (tid >> 5) << 3;
    float2 acc[8];
#pragma unroll
    for (int j = 0; j < 8; j++) acc[j] = make_float2(0.f, 0.f);
    for (int i = 0; i < CINN; i++) {
        float2 xv = sX[i][ky];
#pragma unroll
        for (int j = 0; j < 8; j++) {
            float2 wv = sW[i][cb + j];
            acc[j].x = fmaf(xv.x, wv.x, fmaf(-xv.y, wv.y, acc[j].x));
            acc[j].y = fmaf(xv.x, wv.y, fmaf( xv.y, wv.x, acc[j].y));
        }
    }
#pragma unroll
    for (int j = 0; j < 8; j++)
        g_T[((b * COUTT + cb + j) * KXN + kxi) * M2N + ky] = acc[j];
}

// ---------------- K3b (FFMA): OutF = sum_c t * wy ----------------
__global__ void __launch_bounds__(256) k3b_mixy(const float* __restrict__ wy) {
    __shared__ float2 sT[32][KXN];
    __shared__ float2 sWy[32][COUTT];
    const int tid = threadIdx.x;
    const int ky = blockIdx.x, b = blockIdx.y;
    const int kxi = tid & 63;
    const int ob = (tid >> 6) << 4;
    const float2* wyp = (const float2*)wy;

    float2 acc[16];
#pragma unroll
    for (int j = 0; j < 16; j++) acc[j] = make_float2(0.f, 0.f);

    for (int cb = 0; cb < COUTT; cb += 32) {
        __syncthreads();
        for (int idx = tid; idx < 32 * KXN; idx += 256) {
            int cl = idx >> 6, kk = idx & 63;
            sT[cl][kk] = g_T[((b * COUTT + cb + cl) * KXN + kk) * M2N + ky];
        }
        for (int idx = tid; idx < 32 * COUTT; idx += 256) {
            int cl = idx >> 6, o = idx & 63;
            sWy[cl][o] = wyp[((cb + cl) * COUTT + o) * M2N + ky];
        }
        __syncthreads();
        for (int cl = 0; cl < 32; cl++) {
            float2 tv = sT[cl][kxi];
#pragma unroll
            for (int j = 0; j < 16; j++) {
                float2 wv = sWy[cl][ob + j];
                acc[j].x = fmaf(tv.x, wv.x, fmaf(-tv.y, wv.y, acc[j].x));
                acc[j].y = fmaf(tv.x, wv.y, fmaf( tv.y, wv.x, acc[j].y));
            }
        }
    }
#pragma unroll
    for (int j = 0; j < 16; j++)
        g_OutF[((b * COUTT + ob + j) * KXN + kxi) * M2N + ky] = acc[j];
}

// ---------------- S5: Z = A5 @ OutFslab  (per (b,o): M=512, K=128, N=32) ----------------
__global__ void __launch_bounds__(256) s5_invh() {
    __shared__ float sAh[256][17];
    __shared__ float sAl[256][17];
    __shared__ float sFh[8][66];
    __shared__ float sFl[8][66];
    const int tid = threadIdx.x, warp = tid >> 5, lane = tid & 31;
    const int g = lane >> 2, tg = lane & 3;
    const int mh = blockIdx.x, bo = blockIdx.y;

    const float* outf = (const float*)g_OutF + (size_t)bo * 4096;

    float c[2][4][4];
#pragma unroll
    for (int a = 0; a < 2; a++)
#pragma unroll
        for (int i = 0; i < 4; i++)
#pragma unroll
            for (int j = 0; j < 4; j++) c[a][i][j] = 0.f;

    for (int kc = 0; kc < 8; kc++) {
        __syncthreads();
        for (int i = tid; i < 256 * 16; i += 256) {
            int row = i >> 4, col = i & 15;
            sAh[row][col] = g_A5h[(mh * 256 + row) * 128 + kc * 16 + col];
            sAl[row][col] = g_A5l[(mh * 256 + row) * 128 + kc * 16 + col];
        }
        // split this kc's 8 OutF rows (kxi = kc*8 .. kc*8+7) once
        for (int i = tid; i < 8 * 64; i += 256) {
            int r = i >> 6, cc = i & 63;
            split2f(outf[(kc * 8 + r) * 64 + cc], sFh[r][cc], sFl[r][cc]);
        }
        __syncthreads();
#pragma unroll
        for (int ks = 0; ks < 2; ks++) {
            int l0 = (ks * 8 + tg) >> 1, l1 = (ks * 8 + tg + 4) >> 1;
            int par = tg & 1;
            unsigned bharr[4][2], blarr[4][2];
#pragma unroll
            for (int nt = 0; nt < 4; nt++) {
                int n = nt * 8 + g;
                bharr[nt][0] = B(sFh[l0][2 * n + par]);
                bharr[nt][1] = B(sFh[l1][2 * n + par]);
                blarr[nt][0] = B(sFl[l0][2 * n + par]);
                blarr[nt][1] = B(sFl[l1][2 * n + par]);
            }
#pragma unroll
            for (int mt = 0; mt < 2; mt++) {
                int r = warp * 32 + mt * 16;
                unsigned ah[4], al[4];
                ah[0] = B(sAh[r + g    ][ks * 8 + tg    ]);
                ah[1] = B(sAh[r + g + 8][ks * 8 + tg    ]);
                ah[2] = B(sAh[r + g    ][ks * 8 + tg + 4]);
                ah[3] = B(sAh[r + g + 8][ks * 8 + tg + 4]);
                al[0] = B(sAl[r + g    ][ks * 8 + tg    ]);
                al[1] = B(sAl[r + g + 8][ks * 8 + tg    ]);
                al[2] = B(sAl[r + g    ][ks * 8 + tg + 4]);
                al[3] = B(sAl[r + g + 8][ks * 8 + tg + 4]);
#pragma unroll
                for (int nt = 0; nt < 4; nt++)
                    mma3(c[mt][nt], ah, al, bharr[nt], blarr[nt]);
            }
        }
    }
    float* zh = g_Zh + (size_t)bo * 16384;
    float* zl = g_Zl + (size_t)bo * 16384;
#pragma unroll
    for (int mt = 0; mt < 2; mt++)
#pragma unroll
        for (int nt = 0; nt < 4; nt++) {
            int m0 = mh * 256 + warp * 32 + mt * 16 + g, m1 = m0 + 8;
            int n0 = nt * 8 + 2 * tg, n1 = n0 + 1;
            float h0, l0f, h1, l1f, h2, l2f, h3, l3f;
            split2f(c[mt][nt][0], h0, l0f); split2f(c[mt][nt][1], h1, l1f);
            split2f(c[mt][nt][2], h2, l2f); split2f(c[mt][nt][3], h3, l3f);
            zh[(m0 >> 1) * 64 + 2 * n0 + (m0 & 1)] = h0;
            zl[(m0 >> 1) * 64 + 2 * n0 + (m0 & 1)] = l0f;
            zh[(m0 >> 1) * 64 + 2 * n1 + (m0 & 1)] = h1;
            zl[(m0 >> 1) * 64 + 2 * n1 + (m0 & 1)] = l1f;
            zh[(m1 >> 1) * 64 + 2 * n0 + (m1 & 1)] = h2;
            zl[(m1 >> 1) * 64 + 2 * n0 + (m1 & 1)] = l2f;
            zh[(m1 >> 1) * 64 + 2 * n1 + (m1 & 1)] = h3;
            zl[(m1 >> 1) * 64 + 2 * n1 + (m1 & 1)] = l3f;
        }
}

// ---------------- S6: out = Zslab @ C6  (per (b,o): M=256, K=64, N=256) ----------------
__global__ void __launch_bounds__(256) s6_invw(float* __restrict__ out) {
    __shared__ float sZh[128][17];
    __shared__ float sZl[128][17];
    __shared__ float sCh[16][129];
    __shared__ float sCl[16][129];
    const int tid = threadIdx.x, warp = tid >> 5, lane = tid & 31;
    const int g = lane >> 2, tg = lane & 3;
    const int mt2 = blockIdx.x, nt2 = blockIdx.y, bo = blockIdx.z;

    float c[16][4];
#pragma unroll
    for (int i = 0; i < 16; i++)
#pragma unroll
        for (int j = 0; j < 4; j++) c[i][j] = 0.f;

    const float* zh = g_Zh + (size_t)bo * 16384;
    const float* zl = g_Zl + (size_t)bo * 16384;
    for (int kc = 0; kc < 4; kc++) {
        __syncthreads();
        for (int i = tid; i < 128 * 16; i += 256) {
            int row = i >> 4, col = i & 15;
            sZh[row][col] = zh[(mt2 * 128 + row) * 64 + kc * 16 + col];
            sZl[row][col] = zl[(mt2 * 128 + row) * 64 + kc * 16 + col];
        }
        for (int i = tid; i < 16 * 128; i += 256) {
            int k = i >> 7, n = i & 127;
            sCh[k][n] = g_C6h[(kc * 16 + k) * 256 + nt2 * 128 + n];
            sCl[k][n] = g_C6l[(kc * 16 + k) * 256 + nt2 * 128 + n];
        }
        __syncthreads();
#pragma unroll
        for (int ks = 0; ks < 2; ks++) {
            unsigned ah[4], al[4];
            ah[0] = B(sZh[warp * 16 + g    ][ks * 8 + tg    ]);
            ah[1] = B(sZh[warp * 16 + g + 8][ks * 8 + tg    ]);
            ah[2] = B(sZh[warp * 16 + g    ][ks * 8 + tg + 4]);
            ah[3] = B(sZh[warp * 16 + g + 8][ks * 8 + tg + 4]);
            al[0] = B(sZl[warp * 16 + g    ][ks * 8 + tg    ]);
            al[1] = B(sZl[warp * 16 + g + 8][ks * 8 + tg    ]);
            al[2] = B(sZl[warp * 16 + g    ][ks * 8 + tg + 4]);
            al[3] = B(sZl[warp * 16 + g + 8][ks * 8 + tg + 4]);
#pragma unroll
            for (int nt = 0; nt < 16; nt++) {
                unsigned bh[2], bl[2];
                bh[0] = B(sCh[ks * 8 + tg    ][nt * 8 + g]);
                bh[1] = B(sCh[ks * 8 + tg + 4][nt * 8 + g]);
                bl[0] = B(sCl[ks * 8 + tg    ][nt * 8 + g]);
                bl[1] = B(sCl[ks * 8 + tg + 4][nt * 8 + g]);
                mma3(c[nt], ah, al, bh, bl);
            }
        }
    }
    float* orow = out + (size_t)bo * 65536;
#pragma unroll
    for (int nt = 0; nt < 16; nt++) {
        int h = mt2 * 128 + warp * 16 + g;
        int w = nt2 * 128 + nt * 8 + 2 * tg;
        *(float2*)&orow[(h)     * 256 + w] = make_float2(c[nt][0], c[nt][1]);
        *(float2*)&orow[(h + 8) * 256 + w] = make_float2(c[nt][2], c[nt][3]);
    }
}

extern "C" void kernel_launch(void* const* d_in, const int* in_sizes, int n_in,
                              void* d_out, int out_size) {
    const float* x   = (const float*)d_in[0];
    const float* wx1 = (const float*)d_in[1];
    const float* wx2 = (const float*)d_in[2];
    const float* wy  = (const float*)d_in[3];
    float* out = (float*)d_out;

    fill_B1<<<64, 256>>>();
    fill_A2<<<256, 256>>>();
    fill_A5<<<256, 256>>>();
    fill_C6<<<64, 256>>>();

    s1_wdft<<<2048, 256>>>(x);                 // W-DFT
    s2_hdft<<<1024, 256>>>();                  // H-DFT
    k3a_mixx<<<dim3(KXN, BB), 256>>>(wx1, wx2);
    k3b_mixy<<<dim3(M2N, BB), 256>>>(wy);
    s5_invh<<<dim3(2, 1024), 256>>>();         // inverse H
    s6_invw<<<dim3(2, 2, 1024), 256>>>(out);   // inverse W (irfft)
}